// round 6
// baseline (speedup 1.0000x reference)
#include <cuda_runtime.h>
#include <cstdint>

// ---------------------------------------------------------------------------
// StressGCN: 4-layer GCN, N=100000 nodes, E=1.6M edges, IN_C=128, HID=256.
// h = relu(LN(agg(h@W)*dis + b)) x4, bracketed by encoder / lin1+relu / lin2.
// agg[c] = sum_{(r,c) in edges} (hw[r]*dis[r]) + hw[c]*dis[c]  (self loop)
// ---------------------------------------------------------------------------

#define NNODES   100000
#define IN_C     128
#define HID      256
#define NLAYERS  4
#define LN_EPS   1e-5f

// Scratch (device globals: allocation is forbidden)
__device__ float g_h  [(size_t)NNODES * HID];      // current features
__device__ float g_hw [(size_t)NNODES * HID];      // scaled h@W (gather source)
__device__ float g_agg[(size_t)NNODES * HID];      // aggregation target
__device__ float g_h1 [(size_t)NNODES * (HID/2)];  // lin1 output
__device__ float g_dis[NNODES];
__device__ int   g_deg[NNODES];
__device__ int   g_is32;                           // 1 if edge_index is int32

// ---------------------------------------------------------------------------
// Edge-index dtype probe: under an int64 read, genuine int64 indices are all
// in [0, N); int32 data read as int64 packs two lanes -> values >= 2^32 (or
// otherwise out of range) almost surely within the probe window.
// ---------------------------------------------------------------------------
__global__ void k_detect(const long long* __restrict__ ei, int nsamp, int N) {
    __shared__ int bad;
    if (threadIdx.x == 0) bad = 0;
    __syncthreads();
    for (int i = threadIdx.x; i < nsamp; i += blockDim.x) {
        long long v = ei[i];
        if (v < 0 || v >= (long long)N) bad = 1;
    }
    __syncthreads();
    if (threadIdx.x == 0) g_is32 = bad;
}

__device__ __forceinline__ int edge_at(const void* ei, size_t pos, int is32) {
    return is32 ? ((const int*)ei)[pos]
                : (int)(((const long long*)ei)[pos]);
}

// ---------------------------------------------------------------------------
// Degree / normalization
// ---------------------------------------------------------------------------
__global__ void k_deg_init(int n) {
    int i = blockIdx.x * blockDim.x + threadIdx.x;
    if (i < n) g_deg[i] = 1;  // self loop
}

__global__ void k_deg_count(const void* __restrict__ ei, int E, int N) {
    int e = blockIdx.x * blockDim.x + threadIdx.x;
    if (e >= E) return;
    int is32 = g_is32;
    int c = edge_at(ei, (size_t)E + e, is32);   // target
    if ((unsigned)c < (unsigned)N)
        atomicAdd(&g_deg[c], 1);
}

__global__ void k_dis(int n) {
    int i = blockIdx.x * blockDim.x + threadIdx.x;
    if (i < n) g_dis[i] = rsqrtf((float)g_deg[i]);
}

// ---------------------------------------------------------------------------
// SGEMM: C[M,Nc] = A[M,K] @ B[K,Nc], tiled 128x128x16, 256 threads, 8x8/thread
// mode 0: g_h   = C + bias               (encoder)
// mode 1: g_hw = g_agg = C * dis[m]      (conv: pre-scale + self-loop init)
// mode 2: g_h1  = relu(C + bias)         (lin1)
// Aext == nullptr -> A = g_h
// ---------------------------------------------------------------------------
#define BM 128
#define BN 128
#define BKK 16

__global__ void __launch_bounds__(256)
k_gemm(const float* __restrict__ Aext, const float* __restrict__ B,
       const float* __restrict__ bias, int M, int K, int Nc, int mode) {
    const float* __restrict__ A = Aext ? Aext : g_h;

    __shared__ float As[BKK][BM + 4];
    __shared__ float Bs[BKK][BN + 4];

    const int m0 = blockIdx.x * BM;
    const int n0 = blockIdx.y * BN;
    const int tid = threadIdx.x;
    const int tr = tid >> 4;    // 0..15
    const int tc = tid & 15;    // 0..15

    float acc[8][8];
#pragma unroll
    for (int i = 0; i < 8; i++)
#pragma unroll
        for (int j = 0; j < 8; j++) acc[i][j] = 0.f;

    for (int k0 = 0; k0 < K; k0 += BKK) {
        // A tile: 128x16 = 512 float4, 2 per thread, stored transposed
#pragma unroll
        for (int l = 0; l < 2; l++) {
            int f = tid * 2 + l;
            int row = f >> 2;
            int c4 = (f & 3) * 4;
            float4 v = make_float4(0.f, 0.f, 0.f, 0.f);
            int m = m0 + row;
            if (m < M) v = *(const float4*)(A + (size_t)m * K + k0 + c4);
            As[c4 + 0][row] = v.x;
            As[c4 + 1][row] = v.y;
            As[c4 + 2][row] = v.z;
            As[c4 + 3][row] = v.w;
        }
        // B tile: 16x128 = 512 float4, 2 per thread
#pragma unroll
        for (int l = 0; l < 2; l++) {
            int f = tid * 2 + l;
            int row = f >> 5;
            int c4 = (f & 31) * 4;
            float4 v = *(const float4*)(B + (size_t)(k0 + row) * Nc + n0 + c4);
            *(float4*)&Bs[row][c4] = v;
        }
        __syncthreads();

#pragma unroll
        for (int k = 0; k < BKK; k++) {
            float ra[8], rb[8];
            *(float4*)(ra)     = *(const float4*)&As[k][tr * 8];
            *(float4*)(ra + 4) = *(const float4*)&As[k][tr * 8 + 4];
            *(float4*)(rb)     = *(const float4*)&Bs[k][tc * 8];
            *(float4*)(rb + 4) = *(const float4*)&Bs[k][tc * 8 + 4];
#pragma unroll
            for (int i = 0; i < 8; i++)
#pragma unroll
                for (int j = 0; j < 8; j++)
                    acc[i][j] += ra[i] * rb[j];
        }
        __syncthreads();
    }

    // Epilogue
    const int nbase = n0 + tc * 8;
    float bb[8];
    if (mode != 1) {
#pragma unroll
        for (int j = 0; j < 8; j++) bb[j] = bias[nbase + j];
    }

#pragma unroll
    for (int i = 0; i < 8; i++) {
        int m = m0 + tr * 8 + i;
        if (m >= M) break;
        size_t off = (size_t)m * Nc + nbase;
        if (mode == 0) {
            float4 v0, v1;
            v0.x = acc[i][0] + bb[0]; v0.y = acc[i][1] + bb[1];
            v0.z = acc[i][2] + bb[2]; v0.w = acc[i][3] + bb[3];
            v1.x = acc[i][4] + bb[4]; v1.y = acc[i][5] + bb[5];
            v1.z = acc[i][6] + bb[6]; v1.w = acc[i][7] + bb[7];
            *(float4*)(g_h + off) = v0;
            *(float4*)(g_h + off + 4) = v1;
        } else if (mode == 1) {
            float d = g_dis[m];
            float4 v0, v1;
            v0.x = acc[i][0] * d; v0.y = acc[i][1] * d;
            v0.z = acc[i][2] * d; v0.w = acc[i][3] * d;
            v1.x = acc[i][4] * d; v1.y = acc[i][5] * d;
            v1.z = acc[i][6] * d; v1.w = acc[i][7] * d;
            *(float4*)(g_hw + off) = v0;
            *(float4*)(g_hw + off + 4) = v1;
            *(float4*)(g_agg + off) = v0;      // self-loop init
            *(float4*)(g_agg + off + 4) = v1;
        } else {
            float4 v0, v1;
            v0.x = fmaxf(acc[i][0] + bb[0], 0.f); v0.y = fmaxf(acc[i][1] + bb[1], 0.f);
            v0.z = fmaxf(acc[i][2] + bb[2], 0.f); v0.w = fmaxf(acc[i][3] + bb[3], 0.f);
            v1.x = fmaxf(acc[i][4] + bb[4], 0.f); v1.y = fmaxf(acc[i][5] + bb[5], 0.f);
            v1.z = fmaxf(acc[i][6] + bb[6], 0.f); v1.w = fmaxf(acc[i][7] + bb[7], 0.f);
            *(float4*)(g_h1 + off) = v0;
            *(float4*)(g_h1 + off + 4) = v1;
        }
    }
}

// ---------------------------------------------------------------------------
// Edge scatter: warp per edge. Gather one 1KB row, vector-atomic into target.
// atomicAdd(float4*,float4): sm_90+ intrinsic -> vector RED, no return trip.
// ---------------------------------------------------------------------------
__global__ void __launch_bounds__(256)
k_scatter(const void* __restrict__ ei, int E, int N) {
    int warp = (blockIdx.x * blockDim.x + threadIdx.x) >> 5;
    if (warp >= E) return;
    int lane = threadIdx.x & 31;
    int is32 = g_is32;

    int r = edge_at(ei, warp, is32);
    int c = edge_at(ei, (size_t)E + warp, is32);
    if ((unsigned)r >= (unsigned)N || (unsigned)c >= (unsigned)N) return;

    const float4* __restrict__ src = (const float4*)(g_hw + (size_t)r * HID);
    float4*                    dst = (float4*)(g_agg + (size_t)c * HID);

    float4 v0 = __ldg(src + lane);
    float4 v1 = __ldg(src + lane + 32);
    atomicAdd(dst + lane, v0);
    atomicAdd(dst + lane + 32, v1);
}

// ---------------------------------------------------------------------------
// Finish conv layer: h = relu(LN(agg*dis + conv_b) * g + b), warp per node
// ---------------------------------------------------------------------------
__global__ void __launch_bounds__(256)
k_finish(const float* __restrict__ cb, const float* __restrict__ lg,
         const float* __restrict__ lb, int n) {
    int node = (blockIdx.x * blockDim.x + threadIdx.x) >> 5;
    if (node >= n) return;
    int lane = threadIdx.x & 31;
    size_t base = (size_t)node * HID;

    float d = g_dis[node];
    float4 a0 = *(const float4*)(g_agg + base + lane * 4);
    float4 a1 = *(const float4*)(g_agg + base + lane * 4 + 128);
    float4 c0 = ((const float4*)cb)[lane];
    float4 c1 = ((const float4*)cb)[lane + 32];

    float v[8];
    v[0] = a0.x * d + c0.x; v[1] = a0.y * d + c0.y;
    v[2] = a0.z * d + c0.z; v[3] = a0.w * d + c0.w;
    v[4] = a1.x * d + c1.x; v[5] = a1.y * d + c1.y;
    v[6] = a1.z * d + c1.z; v[7] = a1.w * d + c1.w;

    float s = 0.f, sq = 0.f;
#pragma unroll
    for (int i = 0; i < 8; i++) { s += v[i]; sq += v[i] * v[i]; }
#pragma unroll
    for (int o = 16; o > 0; o >>= 1) {
        s  += __shfl_xor_sync(0xffffffffu, s, o);
        sq += __shfl_xor_sync(0xffffffffu, sq, o);
    }
    float mu = s * (1.f / HID);
    float var = sq * (1.f / HID) - mu * mu;
    float rs = rsqrtf(var + LN_EPS);

    float4 g0 = ((const float4*)lg)[lane];
    float4 g1 = ((const float4*)lg)[lane + 32];
    float4 b0 = ((const float4*)lb)[lane];
    float4 b1 = ((const float4*)lb)[lane + 32];

    float4 o0, o1;
    o0.x = fmaxf((v[0] - mu) * rs * g0.x + b0.x, 0.f);
    o0.y = fmaxf((v[1] - mu) * rs * g0.y + b0.y, 0.f);
    o0.z = fmaxf((v[2] - mu) * rs * g0.z + b0.z, 0.f);
    o0.w = fmaxf((v[3] - mu) * rs * g0.w + b0.w, 0.f);
    o1.x = fmaxf((v[4] - mu) * rs * g1.x + b1.x, 0.f);
    o1.y = fmaxf((v[5] - mu) * rs * g1.y + b1.y, 0.f);
    o1.z = fmaxf((v[6] - mu) * rs * g1.z + b1.z, 0.f);
    o1.w = fmaxf((v[7] - mu) * rs * g1.w + b1.w, 0.f);

    *(float4*)(g_h + base + lane * 4) = o0;
    *(float4*)(g_h + base + lane * 4 + 128) = o1;
}

// ---------------------------------------------------------------------------
// lin2: out[n] = h1[n,:] . w + b, warp per node (128-dot)
// ---------------------------------------------------------------------------
__global__ void __launch_bounds__(256)
k_lin2(const float* __restrict__ w, const float* __restrict__ b,
       float* __restrict__ out, int n) {
    int node = (blockIdx.x * blockDim.x + threadIdx.x) >> 5;
    if (node >= n) return;
    int lane = threadIdx.x & 31;

    float4 h = *(const float4*)(g_h1 + (size_t)node * (HID / 2) + lane * 4);
    float4 wv = ((const float4*)w)[lane];
    float s = h.x * wv.x + h.y * wv.y + h.z * wv.z + h.w * wv.w;
#pragma unroll
    for (int o = 16; o > 0; o >>= 1)
        s += __shfl_xor_sync(0xffffffffu, s, o);
    if (lane == 0) out[node] = s + b[0];
}

// ---------------------------------------------------------------------------
// Launch
// ---------------------------------------------------------------------------
extern "C" void kernel_launch(void* const* d_in, const int* in_sizes, int n_in,
                              void* d_out, int out_size) {
    const float* x      = (const float*)d_in[0];
    const void*  ei     = d_in[1];                 // int32 or int64 — probed
    const float* enc_w  = (const float*)d_in[2];
    const float* enc_b  = (const float*)d_in[3];
    const float* conv_w = (const float*)d_in[4];
    const float* conv_b = (const float*)d_in[5];
    const float* ln_g   = (const float*)d_in[6];
    const float* ln_b   = (const float*)d_in[7];
    const float* lin1_w = (const float*)d_in[8];
    const float* lin1_b = (const float*)d_in[9];
    const float* lin2_w = (const float*)d_in[10];
    const float* lin2_b = (const float*)d_in[11];
    float* out = (float*)d_out;

    const int N = in_sizes[0] / IN_C;    // 100000
    const int E = in_sizes[1] / 2;       // 1600000

    // Probe edge_index dtype (deterministic; depends only on input content).
    // nsamp int64 reads = 2*nsamp int32 slots, safely within 2*E elements.
    int nsamp = (E >= 1024) ? 1024 : (E > 0 ? E : 1);
    k_detect<<<1, 256>>>((const long long*)ei, nsamp, N);

    // Degree + normalization (recomputed every call: deterministic work)
    k_deg_init<<<(N + 255) / 256, 256>>>(N);
    k_deg_count<<<(E + 255) / 256, 256>>>(ei, E, N);
    k_dis<<<(N + 255) / 256, 256>>>(N);

    dim3 g_enc((N + BM - 1) / BM, HID / BN);
    dim3 g_conv((N + BM - 1) / BM, HID / BN);
    dim3 g_lin1((N + BM - 1) / BM, (HID / 2) / BN);

    // Encoder: g_h = x @ enc_w + enc_b
    k_gemm<<<g_enc, 256>>>(x, enc_w, enc_b, N, IN_C, HID, 0);

    const int scatter_blocks = (int)(((size_t)E * 32 + 255) / 256);
    const int node_warp_blocks = (N * 32 + 255) / 256;

    for (int i = 0; i < NLAYERS; i++) {
        // hw = (g_h @ W_i) * dis  ;  agg initialized with self-loop term
        k_gemm<<<g_conv, 256>>>(nullptr, conv_w + (size_t)i * HID * HID,
                                nullptr, N, HID, HID, 1);
        // agg[col] += hw[row]
        k_scatter<<<scatter_blocks, 256>>>(ei, E, N);
        // h = relu(LN(agg*dis + b))
        k_finish<<<node_warp_blocks, 256>>>(conv_b + (size_t)i * HID,
                                            ln_g + (size_t)i * HID,
                                            ln_b + (size_t)i * HID, N);
    }

    // lin1 (+relu), then lin2
    k_gemm<<<g_lin1, 256>>>(nullptr, lin1_w, lin1_b, N, HID, HID / 2, 2);
    k_lin2<<<node_warp_blocks, 256>>>(lin2_w, lin2_b, out, N);
}